// round 7
// baseline (speedup 1.0000x reference)
#include <cuda_runtime.h>
#include <cuda_fp16.h>
#include <cstdint>

#define B_   4
#define CK   64
#define NN   4032
#define NP   4096
#define KH   192            // fp16 split K: A=[hi|lo|hi], B=[hi|hi|lo]
#define SPITCH 400          // smem row pitch in BYTES (odd multiple of 16B)

// ---- device scratch (allocation-free rule) ----
__device__ __align__(16) __half g_hA[(size_t)B_ * NP * KH];   // mk split, K-major
__device__ __align__(16) __half g_hB[(size_t)B_ * NP * KH];   // qk split, K-major
__device__ __align__(16) __half g_S [(size_t)B_ * NP * NP];   // unnormalized p (fp16)
__device__ float g_msq8  [B_ * NP];   // ||mk_n||^2 / 8
__device__ float g_colsum[B_ * NP];   // colsum -> inverted in place

__device__ __forceinline__ uint32_t smem_u32(const void* p) {
    return (uint32_t)__cvta_generic_to_shared(p);
}
__device__ __forceinline__ void ldsm_x4(uint32_t& r0, uint32_t& r1,
                                        uint32_t& r2, uint32_t& r3, uint32_t a) {
    asm volatile("ldmatrix.sync.aligned.m8n8.x4.shared.b16 {%0,%1,%2,%3}, [%4];"
                 : "=r"(r0), "=r"(r1), "=r"(r2), "=r"(r3) : "r"(a));
}
__device__ __forceinline__ void mma16816(float* d, const uint32_t* a,
                                         uint32_t b0, uint32_t b1) {
    asm volatile("mma.sync.aligned.m16n8k16.row.col.f32.f16.f16.f32 "
                 "{%0,%1,%2,%3}, {%4,%5,%6,%7}, {%8,%9}, {%0,%1,%2,%3};"
                 : "+f"(d[0]), "+f"(d[1]), "+f"(d[2]), "+f"(d[3])
                 : "r"(a[0]), "r"(a[1]), "r"(a[2]), "r"(a[3]), "r"(b0), "r"(b1));
}

// ---------------------------------------------------------------------------
// Convert: fp32 -> fp16 hi/lo split, K-major padded scratch; msq/8; zero colsum.
// grid (NP/128, B_, 2): z=0 mk->g_hA (hi|lo|hi), z=1 qk->g_hB (hi|hi|lo).
// ---------------------------------------------------------------------------
__global__ __launch_bounds__(256) void conv_kernel(const float* __restrict__ mk,
                                                   const float* __restrict__ qk) {
    __shared__ float s[64][129];
    const int z = blockIdx.z, b = blockIdx.y, n0 = blockIdx.x * 128;
    const int tid = threadIdx.x;
    const float* src = (z ? qk : mk) + (size_t)b * CK * NN;

    for (int idx = tid; idx < 64 * 128; idx += 256) {
        int c = idx >> 7, n = idx & 127;
        s[c][n] = (n0 + n < NN) ? src[(size_t)c * NN + n0 + n] : 0.f;
    }
    __syncthreads();

    if (z == 0 && tid < 128) {
        float acc = 0.f;
        #pragma unroll
        for (int c = 0; c < 64; ++c) acc += s[c][tid] * s[c][tid];
        g_msq8  [b * NP + n0 + tid] = 0.125f * acc;
        g_colsum[b * NP + n0 + tid] = 0.f;
    }

    __half2* dst = (__half2*)((z ? g_hB : g_hA) + ((size_t)b * NP + n0) * KH);
    for (int idx = tid; idx < 128 * 96; idx += 256) {
        int n = idx / 96, w = idx - n * 96;
        int seg = w >> 5;                 // 0,1,2 (64 halves each)
        int c = (2 * w) & 63;             // channel within segment
        bool want_lo = z ? (seg == 2) : (seg == 1);
        float x0 = s[c][n], x1 = s[c + 1][n];
        __half h0 = __float2half_rn(x0), h1 = __float2half_rn(x1);
        if (want_lo) {
            h0 = __float2half_rn(x0 - __half2float(h0));
            h1 = __float2half_rn(x1 - __half2float(h1));
        }
        dst[(size_t)n * 96 + w] = __halves2half2(h0, h1);
    }
}

// ---------------------------------------------------------------------------
// Pass 1: 128x128 CTA tile GEMM over K=192 via mma.sync m16n8k16 fp16,
// fused exp, fp16 scratch store, fused column sums.
// 8 warps: warp w -> rows (w&3)*32, cols (w>>2)*64.
// k-loop fully unrolled -> ptxas software-pipelines LDSM ahead of HMMA.
// ---------------------------------------------------------------------------
#define SM_A 0
#define SM_B 51200
#define SMEM_P1 102400

__global__ __launch_bounds__(256, 2) void gemm_pass1() {
    extern __shared__ __align__(16) char smem[];
    __shared__ float colred[128];
    const int tid = threadIdx.x;
    const int m0 = blockIdx.x * 128, n0 = blockIdx.y * 128, b = blockIdx.z;
    const int w = tid >> 5, lane = tid & 31;
    const int wm = w & 3, wn = w >> 2;
    const uint32_t sbase = smem_u32(smem);

    if (tid < 128) colred[tid] = 0.f;

    // Load full-K tiles: 128 rows x 384B each (rows contiguous -> linear uint4)
    {
        const uint4* gA = (const uint4*)(g_hA + ((size_t)b * NP + n0) * KH);
        const uint4* gB = (const uint4*)(g_hB + ((size_t)b * NP + m0) * KH);
        #pragma unroll
        for (int t = tid; t < 3072; t += 256) {
            int r = t / 24, j = t - r * 24;
            *(uint4*)(smem + SM_A + r * SPITCH + j * 16) = gA[t];
            *(uint4*)(smem + SM_B + r * SPITCH + j * 16) = gB[t];
        }
    }
    __syncthreads();

    float d[2][8][4];
    #pragma unroll
    for (int i = 0; i < 2; ++i)
        #pragma unroll
        for (int j = 0; j < 8; ++j)
            #pragma unroll
            for (int k = 0; k < 4; ++k) d[i][j][k] = 0.f;

    // ldmatrix lane base addresses (pitch 400B -> conflict-free 8-row groups)
    const uint32_t aAddr = sbase + SM_A +
        (wm * 32 + (lane & 15)) * SPITCH + ((lane >> 4) << 4);
    const uint32_t bAddr = sbase + SM_B +
        (wn * 64 + (lane & 7) + ((lane >> 4) << 3)) * SPITCH + (((lane >> 3) & 1) << 4);

    #pragma unroll
    for (int ks = 0; ks < 12; ++ks) {
        const int kb = ks * 32;            // 16 halves per k-step
        uint32_t a[2][4], bf[4][4];
        #pragma unroll
        for (int mi = 0; mi < 2; ++mi)
            ldsm_x4(a[mi][0], a[mi][1], a[mi][2], a[mi][3],
                    aAddr + kb + mi * 16 * SPITCH);
        #pragma unroll
        for (int p = 0; p < 4; ++p)
            ldsm_x4(bf[p][0], bf[p][1], bf[p][2], bf[p][3],
                    bAddr + kb + p * 16 * SPITCH);
        #pragma unroll
        for (int mi = 0; mi < 2; ++mi)
            #pragma unroll
            for (int p = 0; p < 4; ++p) {
                mma16816(d[mi][2 * p],     a[mi], bf[p][0], bf[p][1]);
                mma16816(d[mi][2 * p + 1], a[mi], bf[p][2], bf[p][3]);
            }
    }

    // Epilogue
    const int g = lane >> 2, t4 = lane & 3;
    float q[2][2]; bool v[2][2];
    #pragma unroll
    for (int mi = 0; mi < 2; ++mi) {
        int r0 = n0 + wm * 32 + mi * 16 + g;
        q[mi][0] = g_msq8[b * NP + r0];
        q[mi][1] = g_msq8[b * NP + r0 + 8];
        v[mi][0] = r0 < NN; v[mi][1] = r0 + 8 < NN;
    }
    const size_t sb = (size_t)b * NP * NP;

    #pragma unroll
    for (int nj = 0; nj < 8; ++nj) {
        float cs0 = 0.f, cs1 = 0.f;
        const int mcol = m0 + wn * 64 + nj * 8 + 2 * t4;
        #pragma unroll
        for (int mi = 0; mi < 2; ++mi) {
            int r0 = n0 + wm * 32 + mi * 16 + g;
            float p00 = __expf(d[mi][nj][0] * 0.25f - q[mi][0]);
            float p01 = __expf(d[mi][nj][1] * 0.25f - q[mi][0]);
            float p10 = __expf(d[mi][nj][2] * 0.25f - q[mi][1]);
            float p11 = __expf(d[mi][nj][3] * 0.25f - q[mi][1]);
            __half2 h0 = __floats2half2_rn(p00, p01);
            __half2 h1 = __floats2half2_rn(p10, p11);
            __stcs((__half2*)(g_S + sb + (size_t)r0 * NP + mcol), h0);
            __stcs((__half2*)(g_S + sb + (size_t)(r0 + 8) * NP + mcol), h1);
            if (v[mi][0]) { cs0 += p00; cs1 += p01; }
            if (v[mi][1]) { cs0 += p10; cs1 += p11; }
        }
        #pragma unroll
        for (int off = 4; off <= 16; off <<= 1) {
            cs0 += __shfl_xor_sync(0xffffffffu, cs0, off);
            cs1 += __shfl_xor_sync(0xffffffffu, cs1, off);
        }
        if (g == 0) {
            atomicAdd(&colred[wn * 64 + nj * 8 + 2 * t4],     cs0);
            atomicAdd(&colred[wn * 64 + nj * 8 + 2 * t4 + 1], cs1);
        }
    }
    __syncthreads();
    if (tid < 128)
        atomicAdd(&g_colsum[b * NP + m0 + tid], colred[tid]);
}

// ---------------------------------------------------------------------------
__global__ void invert_kernel() {
    int i = blockIdx.x * 256 + threadIdx.x;
    if (i < B_ * NP) g_colsum[i] = __frcp_rn(g_colsum[i]);
}

// ---------------------------------------------------------------------------
// Pass 2: out[b][n][m] = fp16->fp32(g_S) * inv_colsum[b][m].
// 16 cols/thread, streaming loads/stores (evict-first: single-touch data).
// ---------------------------------------------------------------------------
__global__ __launch_bounds__(256) void norm_kernel(float* __restrict__ out) {
    size_t idx = (size_t)blockIdx.x * 256 + threadIdx.x;
    const size_t total = (size_t)B_ * NN * (NN / 16);
    if (idx >= total) return;
    int mc = (int)(idx % (NN / 16));
    size_t bn = idx / (NN / 16);
    int n = (int)(bn % NN);
    int b = (int)(bn / NN);
    int m = mc * 16;

    const __half* srow = g_S + ((size_t)b * NP + n) * NP + m;
    float* orow = out + ((size_t)b * NN + n) * NN + m;
    const float* inv = &g_colsum[b * NP + m];

    #pragma unroll
    for (int h = 0; h < 2; ++h) {
        float4 hv = __ldcs((const float4*)(srow + h * 8));
        const __half2* h2 = (const __half2*)&hv;
        float4 i0 = *(const float4*)(inv + h * 8);
        float4 i1 = *(const float4*)(inv + h * 8 + 4);
        float2 f0 = __half22float2(h2[0]), f1 = __half22float2(h2[1]);
        float2 f2 = __half22float2(h2[2]), f3 = __half22float2(h2[3]);
        __stcs((float4*)(orow + h * 8),
               make_float4(f0.x * i0.x, f0.y * i0.y, f1.x * i0.z, f1.y * i0.w));
        __stcs((float4*)(orow + h * 8 + 4),
               make_float4(f2.x * i1.x, f2.y * i1.y, f3.x * i1.z, f3.y * i1.w));
    }
}

// ---------------------------------------------------------------------------
extern "C" void kernel_launch(void* const* d_in, const int* in_sizes, int n_in,
                              void* d_out, int out_size) {
    const float* mk = (const float*)d_in[0];
    const float* qk = (const float*)d_in[1];
    float* out = (float*)d_out;

    cudaFuncSetAttribute(gemm_pass1,
                         cudaFuncAttributeMaxDynamicSharedMemorySize, SMEM_P1);

    dim3 cg(NP / 128, B_, 2);
    conv_kernel<<<cg, 256>>>(mk, qk);

    dim3 gg(NP / 128, NP / 128, B_);
    gemm_pass1<<<gg, 256, SMEM_P1>>>();

    invert_kernel<<<(B_ * NP + 255) / 256, 256>>>();

    size_t total = (size_t)B_ * NN * (NN / 16);
    norm_kernel<<<(unsigned)((total + 255) / 256), 256>>>(out);
}

// round 8
// speedup vs baseline: 1.1816x; 1.1816x over previous
#include <cuda_runtime.h>
#include <cuda_fp16.h>
#include <cstdint>

#define B_   4
#define CK   64
#define NN   4032
#define NP   4096
#define KH   192            // fp16 split K: A=[hi|lo|hi], B=[hi|hi|lo]
#define SPITCH 400          // smem row pitch in BYTES (odd multiple of 16B)

// ---- device scratch (allocation-free rule) ----
__device__ __align__(16) __half g_hA[(size_t)B_ * NP * KH];   // mk split, K-major
__device__ __align__(16) __half g_hB[(size_t)B_ * NP * KH];   // qk split, K-major
__device__ __align__(16) __half g_S [(size_t)B_ * NP * NP];   // unnormalized p (fp16)
__device__ float g_msq8  [B_ * NP];   // ||mk_n||^2 / 8
__device__ float g_colsum[B_ * NP];   // colsum -> inverted in place

__device__ __forceinline__ uint32_t smem_u32(const void* p) {
    return (uint32_t)__cvta_generic_to_shared(p);
}
__device__ __forceinline__ void ldsm_x4(uint32_t& r0, uint32_t& r1,
                                        uint32_t& r2, uint32_t& r3, uint32_t a) {
    asm volatile("ldmatrix.sync.aligned.m8n8.x4.shared.b16 {%0,%1,%2,%3}, [%4];"
                 : "=r"(r0), "=r"(r1), "=r"(r2), "=r"(r3) : "r"(a));
}
__device__ __forceinline__ void mma16816(float* d, const uint32_t* a,
                                         uint32_t b0, uint32_t b1) {
    asm volatile("mma.sync.aligned.m16n8k16.row.col.f32.f16.f16.f32 "
                 "{%0,%1,%2,%3}, {%4,%5,%6,%7}, {%8,%9}, {%0,%1,%2,%3};"
                 : "+f"(d[0]), "+f"(d[1]), "+f"(d[2]), "+f"(d[3])
                 : "r"(a[0]), "r"(a[1]), "r"(a[2]), "r"(a[3]), "r"(b0), "r"(b1));
}
__device__ __forceinline__ void cp16(uint32_t dst, const void* src) {
    asm volatile("cp.async.cg.shared.global [%0], [%1], 16;"
                 :: "r"(dst), "l"(src) : "memory");
}

// ---------------------------------------------------------------------------
// Convert: fp32 -> fp16 hi/lo split, K-major padded scratch; msq/8; zero colsum.
// grid (NP/128, B_, 2): z=0 mk->g_hA (hi|lo|hi), z=1 qk->g_hB (hi|hi|lo).
// ---------------------------------------------------------------------------
__global__ __launch_bounds__(256) void conv_kernel(const float* __restrict__ mk,
                                                   const float* __restrict__ qk) {
    __shared__ float s[64][129];
    const int z = blockIdx.z, b = blockIdx.y, n0 = blockIdx.x * 128;
    const int tid = threadIdx.x;
    const float* src = (z ? qk : mk) + (size_t)b * CK * NN;

    for (int idx = tid; idx < 64 * 128; idx += 256) {
        int c = idx >> 7, n = idx & 127;
        s[c][n] = (n0 + n < NN) ? src[(size_t)c * NN + n0 + n] : 0.f;
    }
    __syncthreads();

    if (z == 0 && tid < 128) {
        float acc = 0.f;
        #pragma unroll
        for (int c = 0; c < 64; ++c) acc += s[c][tid] * s[c][tid];
        g_msq8  [b * NP + n0 + tid] = 0.125f * acc;
        g_colsum[b * NP + n0 + tid] = 0.f;
    }

    __half2* dst = (__half2*)((z ? g_hB : g_hA) + ((size_t)b * NP + n0) * KH);
    for (int idx = tid; idx < 128 * 96; idx += 256) {
        int n = idx / 96, w = idx - n * 96;
        int seg = w >> 5;                 // 0,1,2 (64 halves each)
        int c = (2 * w) & 63;             // channel within segment
        bool want_lo = z ? (seg == 2) : (seg == 1);
        float x0 = s[c][n], x1 = s[c + 1][n];
        __half h0 = __float2half_rn(x0), h1 = __float2half_rn(x1);
        if (want_lo) {
            h0 = __float2half_rn(x0 - __half2float(h0));
            h1 = __float2half_rn(x1 - __half2float(h1));
        }
        dst[(size_t)n * 96 + w] = __halves2half2(h0, h1);
    }
}

// ---------------------------------------------------------------------------
// Pass 1: 128x128 CTA tile GEMM over K=192 via mma.sync m16n8k16 fp16.
// Operands staged via cp.async in 3 K-chunks (commit-group per chunk) so
// chunk-c MMAs overlap chunk c+1..2 global->smem traffic.
// 8 warps: warp w -> rows (w&3)*32, cols (w>>2)*64.
// ---------------------------------------------------------------------------
#define SM_A 0
#define SM_B 51200
#define SMEM_P1 102400

__global__ __launch_bounds__(256, 2) void gemm_pass1() {
    extern __shared__ __align__(16) char smem[];
    __shared__ float colred[128];
    const int tid = threadIdx.x;
    const int m0 = blockIdx.x * 128, n0 = blockIdx.y * 128, b = blockIdx.z;
    const int w = tid >> 5, lane = tid & 31;
    const int wm = w & 3, wn = w >> 2;
    const uint32_t sbase = smem_u32(smem);

    if (tid < 128) colred[tid] = 0.f;

    // Issue all operand loads: 3 chunks x (A 1024 + B 1024) 16B cp.async ops.
    {
        const uint4* gA = (const uint4*)(g_hA + ((size_t)b * NP + n0) * KH);
        const uint4* gB = (const uint4*)(g_hB + ((size_t)b * NP + m0) * KH);
        const int r = tid >> 3, j = tid & 7;           // r:0..31, j:0..7
        #pragma unroll
        for (int c = 0; c < 3; ++c) {
            #pragma unroll
            for (int i = 0; i < 4; ++i) {              // rows r, r+32, r+64, r+96
                int rr = r + i * 32;
                int jj = 8 * c + j;                    // uint4 index within row
                cp16(sbase + SM_A + rr * SPITCH + jj * 16, gA + (size_t)rr * 24 + jj);
                cp16(sbase + SM_B + rr * SPITCH + jj * 16, gB + (size_t)rr * 24 + jj);
            }
            asm volatile("cp.async.commit_group;" ::: "memory");
        }
    }

    float d[2][8][4];
    #pragma unroll
    for (int i = 0; i < 2; ++i)
        #pragma unroll
        for (int j = 0; j < 8; ++j)
            #pragma unroll
            for (int k = 0; k < 4; ++k) d[i][j][k] = 0.f;

    // ldmatrix lane base addresses (pitch 400B -> conflict-free 8-row groups)
    const uint32_t aAddr = sbase + SM_A +
        (wm * 32 + (lane & 15)) * SPITCH + ((lane >> 4) << 4);
    const uint32_t bAddr = sbase + SM_B +
        (wn * 64 + (lane & 7) + ((lane >> 4) << 3)) * SPITCH + (((lane >> 3) & 1) << 4);

    #pragma unroll
    for (int c = 0; c < 3; ++c) {
        if (c == 0)      asm volatile("cp.async.wait_group 2;" ::: "memory");
        else if (c == 1) asm volatile("cp.async.wait_group 1;" ::: "memory");
        else             asm volatile("cp.async.wait_group 0;" ::: "memory");
        __syncthreads();

        #pragma unroll
        for (int k4 = 0; k4 < 4; ++k4) {
            const int kb = (c * 4 + k4) * 32;          // byte offset within row
            uint32_t a[2][4], bf[4][4];
            #pragma unroll
            for (int mi = 0; mi < 2; ++mi)
                ldsm_x4(a[mi][0], a[mi][1], a[mi][2], a[mi][3],
                        aAddr + kb + mi * 16 * SPITCH);
            #pragma unroll
            for (int p = 0; p < 4; ++p)
                ldsm_x4(bf[p][0], bf[p][1], bf[p][2], bf[p][3],
                        bAddr + kb + p * 16 * SPITCH);
            #pragma unroll
            for (int mi = 0; mi < 2; ++mi)
                #pragma unroll
                for (int p = 0; p < 4; ++p) {
                    mma16816(d[mi][2 * p],     a[mi], bf[p][0], bf[p][1]);
                    mma16816(d[mi][2 * p + 1], a[mi], bf[p][2], bf[p][3]);
                }
        }
    }

    // Epilogue
    const int g = lane >> 2, t4 = lane & 3;
    float q[2][2]; bool v[2][2];
    #pragma unroll
    for (int mi = 0; mi < 2; ++mi) {
        int r0 = n0 + wm * 32 + mi * 16 + g;
        q[mi][0] = g_msq8[b * NP + r0];
        q[mi][1] = g_msq8[b * NP + r0 + 8];
        v[mi][0] = r0 < NN; v[mi][1] = r0 + 8 < NN;
    }
    const size_t sb = (size_t)b * NP * NP;

    #pragma unroll
    for (int nj = 0; nj < 8; ++nj) {
        float cs0 = 0.f, cs1 = 0.f;
        const int mcol = m0 + wn * 64 + nj * 8 + 2 * t4;
        #pragma unroll
        for (int mi = 0; mi < 2; ++mi) {
            int r0 = n0 + wm * 32 + mi * 16 + g;
            float p00 = __expf(d[mi][nj][0] * 0.25f - q[mi][0]);
            float p01 = __expf(d[mi][nj][1] * 0.25f - q[mi][0]);
            float p10 = __expf(d[mi][nj][2] * 0.25f - q[mi][1]);
            float p11 = __expf(d[mi][nj][3] * 0.25f - q[mi][1]);
            __half2 h0 = __floats2half2_rn(p00, p01);
            __half2 h1 = __floats2half2_rn(p10, p11);
            __stcs((__half2*)(g_S + sb + (size_t)r0 * NP + mcol), h0);
            __stcs((__half2*)(g_S + sb + (size_t)(r0 + 8) * NP + mcol), h1);
            if (v[mi][0]) { cs0 += p00; cs1 += p01; }
            if (v[mi][1]) { cs0 += p10; cs1 += p11; }
        }
        #pragma unroll
        for (int off = 4; off <= 16; off <<= 1) {
            cs0 += __shfl_xor_sync(0xffffffffu, cs0, off);
            cs1 += __shfl_xor_sync(0xffffffffu, cs1, off);
        }
        if (g == 0) {
            atomicAdd(&colred[wn * 64 + nj * 8 + 2 * t4],     cs0);
            atomicAdd(&colred[wn * 64 + nj * 8 + 2 * t4 + 1], cs1);
        }
    }
    __syncthreads();
    if (tid < 128)
        atomicAdd(&g_colsum[b * NP + m0 + tid], colred[tid]);
}

// ---------------------------------------------------------------------------
__global__ void invert_kernel() {
    int i = blockIdx.x * 256 + threadIdx.x;
    if (i < B_ * NP) g_colsum[i] = __frcp_rn(g_colsum[i]);
}

// ---------------------------------------------------------------------------
// Pass 2: out = fp16->fp32(g_S) * inv_colsum[b][m].  (R6 shape: 8 cols/thread,
// plain loads/stores — measured 64.1us / 65% DRAM; R7's 16-col variant regressed.)
// ---------------------------------------------------------------------------
__global__ __launch_bounds__(256) void norm_kernel(float* __restrict__ out) {
    size_t idx = (size_t)blockIdx.x * 256 + threadIdx.x;
    const size_t total = (size_t)B_ * NN * (NN / 8);
    if (idx >= total) return;
    int mc = (int)(idx % (NN / 8));
    size_t bn = idx / (NN / 8);
    int n = (int)(bn % NN);
    int b = (int)(bn / NN);
    int m = mc * 8;

    uint4 hv = *(const uint4*)(g_S + ((size_t)b * NP + n) * NP + m);
    const __half2* h2 = (const __half2*)&hv;
    float4 i0 = *(const float4*)&g_colsum[b * NP + m];
    float4 i1 = *(const float4*)&g_colsum[b * NP + m + 4];
    float2 f0 = __half22float2(h2[0]), f1 = __half22float2(h2[1]);
    float2 f2 = __half22float2(h2[2]), f3 = __half22float2(h2[3]);

    float* orow = out + ((size_t)b * NN + n) * NN + m;
    *(float4*)orow       = make_float4(f0.x * i0.x, f0.y * i0.y, f1.x * i0.z, f1.y * i0.w);
    *(float4*)(orow + 4) = make_float4(f2.x * i1.x, f2.y * i1.y, f3.x * i1.z, f3.y * i1.w);
}

// ---------------------------------------------------------------------------
extern "C" void kernel_launch(void* const* d_in, const int* in_sizes, int n_in,
                              void* d_out, int out_size) {
    const float* mk = (const float*)d_in[0];
    const float* qk = (const float*)d_in[1];
    float* out = (float*)d_out;

    cudaFuncSetAttribute(gemm_pass1,
                         cudaFuncAttributeMaxDynamicSharedMemorySize, SMEM_P1);

    dim3 cg(NP / 128, B_, 2);
    conv_kernel<<<cg, 256>>>(mk, qk);

    dim3 gg(NP / 128, NP / 128, B_);
    gemm_pass1<<<gg, 256, SMEM_P1>>>();

    invert_kernel<<<(B_ * NP + 255) / 256, 256>>>();

    size_t total = (size_t)B_ * NN * (NN / 8);
    norm_kernel<<<(unsigned)((total + 255) / 256), 256>>>(out);
}